// round 4
// baseline (speedup 1.0000x reference)
#include <cuda_runtime.h>
#include <math.h>

#define Bz 32
#define Tz 512
#define Jz 128
#define Dz 256
#define Gz 768   // 3*D

// ------------------------- device scratch (no allocs allowed) -------------------------
__device__ float g_gi[4][Tz*Bz*Gz];      // long instances, scan order [s][b][g]
__device__ float g_gic[2][Jz*Bz*Gz];     // cmnt instances
__device__ float g_ctx[2][Bz*Tz*2*Dz];   // bigru out, w2-scaled: [b][t][2D]
__device__ float g_cm[Bz*Jz*2*Dz];       // cmnt bigru out, raw
__device__ float g_H[6][2][Bz*Dz];       // double-buffered hidden state
__device__ float g_S[2][Bz*Tz*Jz];       // similarity scores
__device__ float g_Sd[Bz*2*Jz];          // S_diff
__device__ unsigned g_cnt[8];            // per-instance step barriers

// ------------------------- init: zero H + barriers each launch -------------------------
__global__ void k_init() {
    int id = blockIdx.x * blockDim.x + threadIdx.x;
    float* H = &g_H[0][0][0];
    for (int i = id; i < 6*2*Bz*Dz; i += gridDim.x*blockDim.x) H[i] = 0.f;
    if (id < 8) g_cnt[id] = 0u;
}

// ------------- gi = emb[token] @ wih^T + bih (gather-fused tiled SGEMM) -------------
// grid: (row tiles 256, col tiles 12, inst 6); 64x64 tile, K=256, 256 thr, 4x4 micro
__global__ __launch_bounds__(256) void k_gi(
    const int* __restrict__ cm_tok, const int* __restrict__ src_tok,
    const int* __restrict__ tgt_tok, const float* __restrict__ emb,
    const float* __restrict__ wihf, const float* __restrict__ bihf,
    const float* __restrict__ wihb, const float* __restrict__ bihb)
{
    const int inst = blockIdx.z;
    const int dir  = inst & 1;
    const int seq  = inst >> 1;                 // 0 src, 1 tgt, 2 cmnt
    const int Tlen = (seq == 2) ? Jz : Tz;
    const int rows = Tlen * Bz;
    const int rb = blockIdx.x * 64;
    if (rb >= rows) return;
    const int gb = blockIdx.y * 64;

    const int* tok = (seq == 0) ? src_tok : (seq == 1) ? tgt_tok : cm_tok;
    const float* W    = dir ? wihb : wihf;
    const float* bias = dir ? bihb : bihf;
    float* C = (inst < 4) ? &g_gi[inst][0] : &g_gic[inst-4][0];

    __shared__ float As[16][68];
    __shared__ float Bs[16][68];
    const int tid = threadIdx.x;
    const int tx = tid & 15, ty = tid >> 4;
    const int lr = tid >> 2, lk = (tid & 3) * 4;

    // per-thread source row (gather via token)
    int rg = rb + lr;
    int s  = rg >> 5, bb = rg & 31;
    int ts = dir ? (Tlen - 1 - s) : s;
    const float* Arow = emb + (size_t)tok[bb*Tlen + ts] * Dz;
    const float* Brow = W   + (size_t)(gb + lr) * Dz;

    float acc[4][4];
#pragma unroll
    for (int i = 0; i < 4; i++)
#pragma unroll
        for (int j = 0; j < 4; j++) acc[i][j] = 0.f;

    for (int k0 = 0; k0 < Dz; k0 += 16) {
        float4 a  = *(const float4*)(Arow + k0 + lk);
        float4 bv = *(const float4*)(Brow + k0 + lk);
        As[lk+0][lr]=a.x;  As[lk+1][lr]=a.y;  As[lk+2][lr]=a.z;  As[lk+3][lr]=a.w;
        Bs[lk+0][lr]=bv.x; Bs[lk+1][lr]=bv.y; Bs[lk+2][lr]=bv.z; Bs[lk+3][lr]=bv.w;
        __syncthreads();
#pragma unroll
        for (int kk = 0; kk < 16; kk++) {
            float4 ra = *(const float4*)&As[kk][ty*4];
            float4 rb4= *(const float4*)&Bs[kk][tx*4];
            float av[4] = {ra.x, ra.y, ra.z, ra.w};
            float bw[4] = {rb4.x, rb4.y, rb4.z, rb4.w};
#pragma unroll
            for (int i = 0; i < 4; i++)
#pragma unroll
                for (int j = 0; j < 4; j++) acc[i][j] += av[i]*bw[j];
        }
        __syncthreads();
    }
#pragma unroll
    for (int i = 0; i < 4; i++) {
        int row = rb + ty*4 + i;
#pragma unroll
        for (int j = 0; j < 4; j++) {
            int g = gb + tx*4 + j;
            C[(size_t)row*Gz + g] = acc[i][j] + bias[g];
        }
    }
}

// ------------------------- persistent GRU scan -------------------------
// grid: nInst*32 CTAs, 64 threads. Each CTA owns 8 h-cols; thread: 4 rows x 1 col x 3 gates.
// smem: Ws[3*8*260] + Hs[32*260] = 58240 B (dynamic)
__global__ __launch_bounds__(64) void k_scan(
    int instBase, int Tlen,
    const float* __restrict__ whhf, const float* __restrict__ whhb,
    const float* __restrict__ bhhf, const float* __restrict__ bhhb,
    const float* __restrict__ w2)
{
    extern __shared__ float sm[];
    float* Ws = sm;                 // [g*8+cs][260]
    float* Hs = sm + 3*8*260;       // [r][260]

    const int inst  = instBase + (blockIdx.x >> 5);
    const int slice = blockIdx.x & 31;
    const int c0 = slice * 8;
    const int dir = inst & 1;
    const float* whh = dir ? whhb : whhf;
    const float* bhh = dir ? bhhb : bhhf;
    const float* gi_base = (instBase == 0) ? &g_gi[inst][0] : &g_gic[inst-4][0];
    float* out_base      = (instBase == 0) ? &g_ctx[inst>>1][0] : &g_cm[0];

    const int tid = threadIdx.x;
    const int cs = tid & 7, rg = tid >> 3;      // col slot, row group (4 rows)
    const int c = c0 + cs;

    // load whh slice into smem (24 rows of 256)
    for (int rr = 0; rr < 24; rr++) {
        int g = rr >> 3, cc = rr & 7;
        const float4* src = (const float4*)(whh + (size_t)(g*256 + c0 + cc)*Dz);
        *(float4*)&Ws[(g*8+cc)*260 + tid*4] = src[tid];
    }
    const float bR = bhh[c], bZ = bhh[256+c], bN = bhh[512+c];
    const float w2c = (instBase == 0) ? w2[dir*256 + c] : 1.0f;
    __syncthreads();

    const float* wr = &Ws[(0*8+cs)*260];
    const float* wz = &Ws[(1*8+cs)*260];
    const float* wn = &Ws[(2*8+cs)*260];

    for (int s = 0; s < Tlen; s++) {
        const float4* Hp = (const float4*)&g_H[inst][s&1][0];
        float*        Hn = &g_H[inst][(s&1)^1][0];
        // load full H_prev (L2 only — bypass potentially-stale L1)
        for (int q = tid; q < 2048; q += 64) {
            float4 v = __ldcg(Hp + q);
            *(float4*)&Hs[(q>>6)*260 + (q&63)*4] = v;
        }
        __syncthreads();

        float aR[4]={0,0,0,0}, aZ[4]={0,0,0,0}, aN[4]={0,0,0,0};
#pragma unroll 4
        for (int k = 0; k < 256; k += 4) {
            float4 vr = *(const float4*)(wr + k);
            float4 vz = *(const float4*)(wz + k);
            float4 vn = *(const float4*)(wn + k);
#pragma unroll
            for (int i = 0; i < 4; i++) {
                float4 x = *(const float4*)&Hs[(rg*4+i)*260 + k];
                aR[i] += x.x*vr.x + x.y*vr.y + x.z*vr.z + x.w*vr.w;
                aZ[i] += x.x*vz.x + x.y*vz.y + x.z*vz.z + x.w*vz.w;
                aN[i] += x.x*vn.x + x.y*vn.y + x.z*vn.z + x.w*vn.w;
            }
        }

        const int tact = dir ? (Tlen - 1 - s) : s;
#pragma unroll
        for (int i = 0; i < 4; i++) {
            int r = rg*4 + i;
            const float* gi = gi_base + (size_t)(s*32 + r)*Gz;
            float gr = gi[c], gz = gi[256+c], gn = gi[512+c];
            float rr2 = 1.f/(1.f + expf(-(gr + aR[i] + bR)));
            float zz  = 1.f/(1.f + expf(-(gz + aZ[i] + bZ)));
            float nn  = tanhf(gn + rr2*(aN[i] + bN));
            float hp  = Hs[r*260 + c];
            float h   = (1.f - zz)*nn + zz*hp;
            __stcg(Hn + r*256 + c, h);
            out_base[((size_t)r*Tlen + tact)*(2*Dz) + dir*256 + c] = h * w2c;
        }
        __syncthreads();
        __threadfence();
        if (tid == 0) {
            atomicAdd(&g_cnt[inst], 1u);
            unsigned target = 32u*(s+1);
            while (*(volatile unsigned*)&g_cnt[inst] < target) { __nanosleep(32); }
        }
        __syncthreads();
    }
}

// ------------- S[b,t,j] = sum_d ctxS[b,t,d]*cm[b,j,d] + action*w2[512] -------------
// grid: (ttile 8, b 32, side 2); tile 64t x 128j, K=512, 256 thr, 4x8 micro
__global__ __launch_bounds__(256) void k_sim(
    const int* __restrict__ src_act, const int* __restrict__ tgt_act,
    const float* __restrict__ w2)
{
    const int side = blockIdx.z;
    const int b    = blockIdx.y;
    const int tb   = blockIdx.x * 64;
    const float* A = &g_ctx[side][(size_t)b*Tz*2*Dz];   // [t][512]
    const float* Bm= &g_cm[(size_t)b*Jz*2*Dz];          // [j][512]
    const int* act = side ? tgt_act : src_act;
    const float wA = w2[2*Dz];

    __shared__ float As[16][68];
    __shared__ float Bs[16][132];
    const int tid = threadIdx.x;
    const int tx = tid & 15, ty = tid >> 4;
    const int lrA = tid >> 2, lkA = (tid & 3) * 4;
    const int lrB = tid >> 1, lkB = (tid & 1) * 8;

    float acc[4][8];
#pragma unroll
    for (int i = 0; i < 4; i++)
#pragma unroll
        for (int j = 0; j < 8; j++) acc[i][j] = 0.f;

    const float* Arow = A + (size_t)(tb + lrA)*(2*Dz);
    const float* Brow = Bm + (size_t)lrB*(2*Dz);

    for (int k0 = 0; k0 < 2*Dz; k0 += 16) {
        float4 a = *(const float4*)(Arow + k0 + lkA);
        As[lkA+0][lrA]=a.x; As[lkA+1][lrA]=a.y; As[lkA+2][lrA]=a.z; As[lkA+3][lrA]=a.w;
        float4 b0 = *(const float4*)(Brow + k0 + lkB);
        float4 b1 = *(const float4*)(Brow + k0 + lkB + 4);
        Bs[lkB+0][lrB]=b0.x; Bs[lkB+1][lrB]=b0.y; Bs[lkB+2][lrB]=b0.z; Bs[lkB+3][lrB]=b0.w;
        Bs[lkB+4][lrB]=b1.x; Bs[lkB+5][lrB]=b1.y; Bs[lkB+6][lrB]=b1.z; Bs[lkB+7][lrB]=b1.w;
        __syncthreads();
#pragma unroll
        for (int kk = 0; kk < 16; kk++) {
            float4 ra = *(const float4*)&As[kk][ty*4];
            float av[4] = {ra.x, ra.y, ra.z, ra.w};
            float4 rb0 = *(const float4*)&Bs[kk][tx*8];
            float4 rb1 = *(const float4*)&Bs[kk][tx*8+4];
            float bw[8] = {rb0.x,rb0.y,rb0.z,rb0.w, rb1.x,rb1.y,rb1.z,rb1.w};
#pragma unroll
            for (int i = 0; i < 4; i++)
#pragma unroll
                for (int j = 0; j < 8; j++) acc[i][j] += av[i]*bw[j];
        }
        __syncthreads();
    }
#pragma unroll
    for (int i = 0; i < 4; i++) {
        int t = tb + ty*4 + i;
        float aterm = (float)act[b*Tz + t] * wA;
        float* Sp = &g_S[side][((size_t)b*Tz + t)*Jz];
#pragma unroll
        for (int j = 0; j < 8; j++) Sp[tx*8 + j] = acc[i][j] + aterm;
    }
}

// --------- per (side,b): m_t = max_j S; w = softmax_t(m); out_j = sum_t w_t S[t,j] ---------
__global__ __launch_bounds__(256) void k_reduce() {
    const int b = blockIdx.x, side = blockIdx.y;
    const float* S = &g_S[side][(size_t)b*Tz*Jz];
    __shared__ float mrow[512];
    __shared__ float red[256];
    const int tid = threadIdx.x;

    for (int t = tid; t < Tz; t += 256) {
        const float4* row = (const float4*)(S + (size_t)t*Jz);
        float m = -3.4e38f;
#pragma unroll 4
        for (int q = 0; q < 32; q++) {
            float4 v = row[q];
            m = fmaxf(m, fmaxf(fmaxf(v.x, v.y), fmaxf(v.z, v.w)));
        }
        mrow[t] = m;
    }
    __syncthreads();
    red[tid] = fmaxf(mrow[tid], mrow[tid+256]);
    __syncthreads();
    for (int st = 128; st > 0; st >>= 1) {
        if (tid < st) red[tid] = fmaxf(red[tid], red[tid+st]);
        __syncthreads();
    }
    float M = red[0];
    __syncthreads();
    float e1 = expf(mrow[tid] - M), e2 = expf(mrow[tid+256] - M);
    mrow[tid] = e1; mrow[tid+256] = e2;
    red[tid] = e1 + e2;
    __syncthreads();
    for (int st = 128; st > 0; st >>= 1) {
        if (tid < st) red[tid] += red[tid+st];
        __syncthreads();
    }
    float inv = 1.f / red[0];
    __syncthreads();
    mrow[tid] *= inv; mrow[tid+256] *= inv;
    __syncthreads();

    const int j = tid & 127, half = tid >> 7;
    float acc = 0.f;
    for (int t = half*256; t < half*256 + 256; t++)
        acc += mrow[t] * S[(size_t)t*Jz + j];
    red[tid] = acc;
    __syncthreads();
    if (tid < 128)
        g_Sd[b*(2*Jz) + side*Jz + j] = red[j] + red[128 + j];
}

// ---------------- result = S_diff @ rank_w + rank_b; emit (result, S_diff) ----------------
__global__ __launch_bounds__(256) void k_final(
    const float* __restrict__ rank_w, const float* __restrict__ rank_b,
    float* __restrict__ out)
{
    const int tid = threadIdx.x;
    for (int i = tid; i < Bz*2*Jz; i += 256) out[32 + i] = g_Sd[i];
    __shared__ float red[256];
    const int b = tid >> 3, l = tid & 7;
    float p = 0.f;
    for (int q = l; q < 2*Jz; q += 8) p += g_Sd[b*(2*Jz) + q] * rank_w[q];
    red[tid] = p;
    __syncthreads();
    if (l == 0) {
        float s = 0.f;
#pragma unroll
        for (int k = 0; k < 8; k++) s += red[b*8 + k];
        out[b] = s + rank_b[0];
    }
}

// ------------------------- launch -------------------------
extern "C" void kernel_launch(void* const* d_in, const int* in_sizes, int n_in,
                              void* d_out, int out_size) {
    const int*   cm_tok = (const int*)  d_in[0];
    const int*   src_t  = (const int*)  d_in[1];
    const int*   tgt_t  = (const int*)  d_in[2];
    const int*   src_a  = (const int*)  d_in[3];
    const int*   tgt_a  = (const int*)  d_in[4];
    const float* emb    = (const float*)d_in[5];
    const float* wihf   = (const float*)d_in[6];
    const float* whhf   = (const float*)d_in[7];
    const float* bihf   = (const float*)d_in[8];
    const float* bhhf   = (const float*)d_in[9];
    const float* wihb   = (const float*)d_in[10];
    const float* whhb   = (const float*)d_in[11];
    const float* bihb   = (const float*)d_in[12];
    const float* bhhb   = (const float*)d_in[13];
    const float* w2     = (const float*)d_in[14];
    const float* rank_w = (const float*)d_in[15];
    const float* rank_b = (const float*)d_in[16];
    float* out = (float*)d_out;

    const int scanSmem = (3*8*260 + 32*260) * sizeof(float);  // 58240
    cudaFuncSetAttribute(k_scan, cudaFuncAttributeMaxDynamicSharedMemorySize, scanSmem);

    k_init<<<96, 256>>>();
    k_gi<<<dim3(256, 12, 6), 256>>>(cm_tok, src_t, tgt_t, emb, wihf, bihf, wihb, bihb);
    k_scan<<<64, 64, scanSmem>>>(4, Jz, whhf, whhb, bhhf, bhhb, w2);   // cmnt fwd+bwd
    k_scan<<<128, 64, scanSmem>>>(0, Tz, whhf, whhb, bhhf, bhhb, w2);  // src/tgt fwd+bwd
    k_sim<<<dim3(8, 32, 2), 256>>>(src_a, tgt_a, w2);
    k_reduce<<<dim3(32, 2), 256>>>();
    k_final<<<1, 256>>>(rank_w, rank_b, out);
}

// round 5
// speedup vs baseline: 2.0194x; 2.0194x over previous
#include <cuda_runtime.h>
#include <math.h>

#define Bz 32
#define Tz 512
#define Jz 128
#define Dz 256
#define Gz 768   // 3*D

// ------------------------- device scratch (no allocs allowed) -------------------------
__device__ float g_gi[4][Tz*Bz*Gz];      // long instances, scan order [s][b][g]
__device__ float g_gic[2][Jz*Bz*Gz];     // cmnt instances
__device__ float g_ctx[2][Bz*Tz*2*Dz];   // bigru out, w2-scaled: [b][t][2D]
__device__ float g_cm[Bz*Jz*2*Dz];       // cmnt bigru out, raw
__device__ float g_H[6][2][Bz*Dz];       // double-buffered hidden state
__device__ float g_S[2][Bz*Tz*Jz];       // similarity scores
__device__ float g_Sd[Bz*2*Jz];          // S_diff
__device__ unsigned g_cnt[8];            // per-instance step barriers

__device__ __forceinline__ float fsig(float x) { return 1.f/(1.f + __expf(-x)); }
__device__ __forceinline__ float ftanh(float x) { return 1.f - 2.f/(1.f + __expf(2.f*x)); }

// ------------------------- init: zero H + barriers each launch -------------------------
__global__ void k_init() {
    int id = blockIdx.x * blockDim.x + threadIdx.x;
    float* H = &g_H[0][0][0];
    for (int i = id; i < 6*2*Bz*Dz; i += gridDim.x*blockDim.x) H[i] = 0.f;
    if (id < 8) g_cnt[id] = 0u;
}

// ------------- gi = emb[token] @ wih^T + bih (gather-fused tiled SGEMM) -------------
// grid: (row tiles 128, col tiles 12, inst 6); 128x64 tile, K=256, 256 thr, 8x4 micro
__global__ __launch_bounds__(256) void k_gi(
    const int* __restrict__ cm_tok, const int* __restrict__ src_tok,
    const int* __restrict__ tgt_tok, const float* __restrict__ emb,
    const float* __restrict__ wihf, const float* __restrict__ bihf,
    const float* __restrict__ wihb, const float* __restrict__ bihb)
{
    const int inst = blockIdx.z;
    const int dir  = inst & 1;
    const int seq  = inst >> 1;                 // 0 src, 1 tgt, 2 cmnt
    const int Tlen = (seq == 2) ? Jz : Tz;
    const int rows = Tlen * Bz;
    const int rb = blockIdx.x * 128;
    if (rb >= rows) return;
    const int gb = blockIdx.y * 64;

    const int* tok = (seq == 0) ? src_tok : (seq == 1) ? tgt_tok : cm_tok;
    const float* W    = dir ? wihb : wihf;
    const float* bias = dir ? bihb : bihf;
    float* C = (inst < 4) ? &g_gi[inst][0] : &g_gic[inst-4][0];

    __shared__ float As[16][132];
    __shared__ float Bs[16][68];
    const int tid = threadIdx.x;
    const int tx = tid & 15, ty = tid >> 4;
    const int lrA = tid >> 1, lkA = (tid & 1) * 8;   // A: row lrA, k halves
    const int lrB = tid >> 2, lkB = (tid & 3) * 4;   // B: row lrB (g), k quarter

    // gather source row
    int rg = rb + lrA;
    int s  = rg >> 5, bb = rg & 31;
    int ts = dir ? (Tlen - 1 - s) : s;
    const float* Arow = emb + (size_t)tok[bb*Tlen + ts] * Dz;
    const float* Brow = W   + (size_t)(gb + lrB) * Dz;

    float acc[8][4];
#pragma unroll
    for (int i = 0; i < 8; i++)
#pragma unroll
        for (int j = 0; j < 4; j++) acc[i][j] = 0.f;

    for (int k0 = 0; k0 < Dz; k0 += 16) {
        float4 a0 = *(const float4*)(Arow + k0 + lkA);
        float4 a1 = *(const float4*)(Arow + k0 + lkA + 4);
        float4 bv = *(const float4*)(Brow + k0 + lkB);
        As[lkA+0][lrA]=a0.x; As[lkA+1][lrA]=a0.y; As[lkA+2][lrA]=a0.z; As[lkA+3][lrA]=a0.w;
        As[lkA+4][lrA]=a1.x; As[lkA+5][lrA]=a1.y; As[lkA+6][lrA]=a1.z; As[lkA+7][lrA]=a1.w;
        Bs[lkB+0][lrB]=bv.x; Bs[lkB+1][lrB]=bv.y; Bs[lkB+2][lrB]=bv.z; Bs[lkB+3][lrB]=bv.w;
        __syncthreads();
#pragma unroll
        for (int kk = 0; kk < 16; kk++) {
            float4 ra0 = *(const float4*)&As[kk][ty*8];
            float4 ra1 = *(const float4*)&As[kk][ty*8+4];
            float4 rb4 = *(const float4*)&Bs[kk][tx*4];
            float av[8] = {ra0.x,ra0.y,ra0.z,ra0.w, ra1.x,ra1.y,ra1.z,ra1.w};
            float bw[4] = {rb4.x,rb4.y,rb4.z,rb4.w};
#pragma unroll
            for (int i = 0; i < 8; i++)
#pragma unroll
                for (int j = 0; j < 4; j++) acc[i][j] += av[i]*bw[j];
        }
        __syncthreads();
    }
    float4 b4 = *(const float4*)(bias + gb + tx*4);
#pragma unroll
    for (int i = 0; i < 8; i++) {
        int row = rb + ty*8 + i;
        float4 v = { acc[i][0]+b4.x, acc[i][1]+b4.y, acc[i][2]+b4.z, acc[i][3]+b4.w };
        *(float4*)&C[(size_t)row*Gz + gb + tx*4] = v;
    }
}

// ------------------------- persistent GRU scan (merged long+cmnt) -------------------------
// grid 192 x 256 thr. bid<128: long (inst 0-3, T=512); bid>=128: cmnt (inst 4-5, T=128).
// CTA owns 8 h-cols. Thread = 4 rows x 1 col x K/4. lane = kq*8+cs (phase-aligned LDS).
// smem: Ws[24*260] + Hs[32*260] = 58240 B dynamic.
__global__ __launch_bounds__(256) void k_scan(
    const float* __restrict__ whhf, const float* __restrict__ whhb,
    const float* __restrict__ bhhf, const float* __restrict__ bhhb,
    const float* __restrict__ w2)
{
    extern __shared__ float sm[];
    float* Ws = sm;                 // [(g*8+cc)*260 + k]
    float* Hs = sm + 24*260;        // [r*260 + k]

    const int bid = blockIdx.x;
    int inst, Tlen;
    const float* gi_base; float* out_base;
    if (bid < 128) {
        inst = bid >> 5; Tlen = Tz;
        gi_base = &g_gi[inst][0]; out_base = &g_ctx[inst>>1][0];
    } else {
        inst = 4 + ((bid - 128) >> 5); Tlen = Jz;
        gi_base = &g_gic[inst-4][0]; out_base = &g_cm[0];
    }
    const int slice = bid & 31;
    const int c0 = slice * 8;
    const int dir = inst & 1;
    const float* whh = dir ? whhb : whhf;
    const float* bhh = dir ? bhhb : bhhf;

    const int tid = threadIdx.x;
    const int rg   = tid >> 5;          // warp id = row group (4 rows)
    const int lane = tid & 31;
    const int kq   = lane >> 3;         // K quarter 0..3
    const int cs   = lane & 7;          // col slot
    const int c    = c0 + cs;
    const int kbase = kq * 64;

    // load whh slice (24 rows x 256) into smem
    for (int q = tid; q < 24*64; q += 256) {
        int row = q >> 6, kk = (q & 63) * 4;
        int g = row >> 3, cc = row & 7;
        *(float4*)&Ws[row*260 + kk] =
            *(const float4*)(whh + (size_t)(g*256 + c0 + cc)*Dz + kk);
    }
    const float bR = bhh[c], bZ = bhh[256+c], bN = bhh[512+c];
    const float w2c = (bid < 128) ? w2[dir*256 + c] : 1.0f;
    __syncthreads();

    const float* wr = &Ws[(0*8+cs)*260 + kbase];
    const float* wz = &Ws[(1*8+cs)*260 + kbase];
    const float* wn = &Ws[(2*8+cs)*260 + kbase];
    unsigned* cnt = &g_cnt[inst];

    for (int s = 0; s < Tlen; s++) {
        // prefetch gi operands (independent of H)
        float gr[4], gz[4], gn[4];
        if (kq == 0) {
#pragma unroll
            for (int i = 0; i < 4; i++) {
                const float* gp = gi_base + (size_t)(s*32 + rg*4 + i)*Gz;
                gr[i] = __ldcs(gp + c);
                gz[i] = __ldcs(gp + 256 + c);
                gn[i] = __ldcs(gp + 512 + c);
            }
        }
        // load H_prev into smem (L2 path — coherent with peer CTAs)
        const float4* Hp = (const float4*)&g_H[inst][s&1][0];
        float*        Hn = &g_H[inst][(s&1)^1][0];
        for (int q = tid; q < 2048; q += 256) {
            float4 v = __ldcg(Hp + q);
            *(float4*)&Hs[(q>>6)*260 + (q&63)*4] = v;
        }
        __syncthreads();

        float aR[4]={0,0,0,0}, aZ[4]={0,0,0,0}, aN[4]={0,0,0,0};
#pragma unroll 4
        for (int k = 0; k < 64; k += 4) {
            float4 vr = *(const float4*)(wr + k);
            float4 vz = *(const float4*)(wz + k);
            float4 vn = *(const float4*)(wn + k);
#pragma unroll
            for (int i = 0; i < 4; i++) {
                float4 x = *(const float4*)&Hs[(rg*4+i)*260 + kbase + k];
                aR[i] += x.x*vr.x + x.y*vr.y + x.z*vr.z + x.w*vr.w;
                aZ[i] += x.x*vz.x + x.y*vz.y + x.z*vz.z + x.w*vz.w;
                aN[i] += x.x*vn.x + x.y*vn.y + x.z*vn.z + x.w*vn.w;
            }
        }
        // reduce K partials across kq (lanes differ by 8,16 — same warp)
#pragma unroll
        for (int i = 0; i < 4; i++) {
            aR[i] += __shfl_xor_sync(0xFFFFFFFFu, aR[i], 8);
            aR[i] += __shfl_xor_sync(0xFFFFFFFFu, aR[i], 16);
            aZ[i] += __shfl_xor_sync(0xFFFFFFFFu, aZ[i], 8);
            aZ[i] += __shfl_xor_sync(0xFFFFFFFFu, aZ[i], 16);
            aN[i] += __shfl_xor_sync(0xFFFFFFFFu, aN[i], 8);
            aN[i] += __shfl_xor_sync(0xFFFFFFFFu, aN[i], 16);
        }

        if (kq == 0) {
            const int tact = dir ? (Tlen - 1 - s) : s;
#pragma unroll
            for (int i = 0; i < 4; i++) {
                int r = rg*4 + i;
                float rr2 = fsig(gr[i] + aR[i] + bR);
                float zz  = fsig(gz[i] + aZ[i] + bZ);
                float nn  = ftanh(gn[i] + rr2*(aN[i] + bN));
                float hp  = Hs[r*260 + c];
                float h   = (1.f - zz)*nn + zz*hp;
                __stcg(Hn + r*256 + c, h);
                out_base[((size_t)r*Tlen + tact)*(2*Dz) + dir*256 + c] = h * w2c;
            }
        }
        __syncthreads();
        __threadfence();
        if (tid == 0) {
            atomicAdd(cnt, 1u);
            unsigned target = 32u*(unsigned)(s+1);
            while (*(volatile unsigned*)cnt < target) { }
        }
        __syncthreads();
    }
}

// ------------- S[b,t,j] = sum_d ctxS[b,t,d]*cm[b,j,d] + action*w2[512] -------------
__global__ __launch_bounds__(256) void k_sim(
    const int* __restrict__ src_act, const int* __restrict__ tgt_act,
    const float* __restrict__ w2)
{
    const int side = blockIdx.z;
    const int b    = blockIdx.y;
    const int tb   = blockIdx.x * 64;
    const float* A = &g_ctx[side][(size_t)b*Tz*2*Dz];   // [t][512]
    const float* Bm= &g_cm[(size_t)b*Jz*2*Dz];          // [j][512]
    const int* act = side ? tgt_act : src_act;
    const float wA = w2[2*Dz];

    __shared__ float As[16][68];
    __shared__ float Bs[16][132];
    const int tid = threadIdx.x;
    const int tx = tid & 15, ty = tid >> 4;
    const int lrA = tid >> 2, lkA = (tid & 3) * 4;
    const int lrB = tid >> 1, lkB = (tid & 1) * 8;

    float acc[4][8];
#pragma unroll
    for (int i = 0; i < 4; i++)
#pragma unroll
        for (int j = 0; j < 8; j++) acc[i][j] = 0.f;

    const float* Arow = A + (size_t)(tb + lrA)*(2*Dz);
    const float* Brow = Bm + (size_t)lrB*(2*Dz);

    for (int k0 = 0; k0 < 2*Dz; k0 += 16) {
        float4 a = *(const float4*)(Arow + k0 + lkA);
        As[lkA+0][lrA]=a.x; As[lkA+1][lrA]=a.y; As[lkA+2][lrA]=a.z; As[lkA+3][lrA]=a.w;
        float4 b0 = *(const float4*)(Brow + k0 + lkB);
        float4 b1 = *(const float4*)(Brow + k0 + lkB + 4);
        Bs[lkB+0][lrB]=b0.x; Bs[lkB+1][lrB]=b0.y; Bs[lkB+2][lrB]=b0.z; Bs[lkB+3][lrB]=b0.w;
        Bs[lkB+4][lrB]=b1.x; Bs[lkB+5][lrB]=b1.y; Bs[lkB+6][lrB]=b1.z; Bs[lkB+7][lrB]=b1.w;
        __syncthreads();
#pragma unroll
        for (int kk = 0; kk < 16; kk++) {
            float4 ra = *(const float4*)&As[kk][ty*4];
            float av[4] = {ra.x, ra.y, ra.z, ra.w};
            float4 rb0 = *(const float4*)&Bs[kk][tx*8];
            float4 rb1 = *(const float4*)&Bs[kk][tx*8+4];
            float bw[8] = {rb0.x,rb0.y,rb0.z,rb0.w, rb1.x,rb1.y,rb1.z,rb1.w};
#pragma unroll
            for (int i = 0; i < 4; i++)
#pragma unroll
                for (int j = 0; j < 8; j++) acc[i][j] += av[i]*bw[j];
        }
        __syncthreads();
    }
#pragma unroll
    for (int i = 0; i < 4; i++) {
        int t = tb + ty*4 + i;
        float aterm = (float)act[b*Tz + t] * wA;
        float* Sp = &g_S[side][((size_t)b*Tz + t)*Jz];
#pragma unroll
        for (int j = 0; j < 8; j++) Sp[tx*8 + j] = acc[i][j] + aterm;
    }
}

// --------- per (side,b): m_t = max_j S; w = softmax_t(m); out_j = sum_t w_t S[t,j] ---------
__global__ __launch_bounds__(256) void k_reduce() {
    const int b = blockIdx.x, side = blockIdx.y;
    const float* S = &g_S[side][(size_t)b*Tz*Jz];
    __shared__ float mrow[512];
    __shared__ float red[256];
    const int tid = threadIdx.x;

    for (int t = tid; t < Tz; t += 256) {
        const float4* row = (const float4*)(S + (size_t)t*Jz);
        float m = -3.4e38f;
#pragma unroll 4
        for (int q = 0; q < 32; q++) {
            float4 v = row[q];
            m = fmaxf(m, fmaxf(fmaxf(v.x, v.y), fmaxf(v.z, v.w)));
        }
        mrow[t] = m;
    }
    __syncthreads();
    red[tid] = fmaxf(mrow[tid], mrow[tid+256]);
    __syncthreads();
    for (int st = 128; st > 0; st >>= 1) {
        if (tid < st) red[tid] = fmaxf(red[tid], red[tid+st]);
        __syncthreads();
    }
    float M = red[0];
    __syncthreads();
    float e1 = __expf(mrow[tid] - M), e2 = __expf(mrow[tid+256] - M);
    mrow[tid] = e1; mrow[tid+256] = e2;
    red[tid] = e1 + e2;
    __syncthreads();
    for (int st = 128; st > 0; st >>= 1) {
        if (tid < st) red[tid] += red[tid+st];
        __syncthreads();
    }
    float inv = 1.f / red[0];
    __syncthreads();
    mrow[tid] *= inv; mrow[tid+256] *= inv;
    __syncthreads();

    const int j = tid & 127, half = tid >> 7;
    float acc = 0.f;
    for (int t = half*256; t < half*256 + 256; t++)
        acc += mrow[t] * S[(size_t)t*Jz + j];
    red[tid] = acc;
    __syncthreads();
    if (tid < 128)
        g_Sd[b*(2*Jz) + side*Jz + j] = red[j] + red[128 + j];
}

// ---------------- result = S_diff @ rank_w + rank_b; emit (result, S_diff) ----------------
__global__ __launch_bounds__(256) void k_final(
    const float* __restrict__ rank_w, const float* __restrict__ rank_b,
    float* __restrict__ out)
{
    const int tid = threadIdx.x;
    for (int i = tid; i < Bz*2*Jz; i += 256) out[32 + i] = g_Sd[i];
    __shared__ float red[256];
    const int b = tid >> 3, l = tid & 7;
    float p = 0.f;
    for (int q = l; q < 2*Jz; q += 8) p += g_Sd[b*(2*Jz) + q] * rank_w[q];
    red[tid] = p;
    __syncthreads();
    if (l == 0) {
        float s = 0.f;
#pragma unroll
        for (int k = 0; k < 8; k++) s += red[b*8 + k];
        out[b] = s + rank_b[0];
    }
}

// ------------------------- launch -------------------------
extern "C" void kernel_launch(void* const* d_in, const int* in_sizes, int n_in,
                              void* d_out, int out_size) {
    const int*   cm_tok = (const int*)  d_in[0];
    const int*   src_t  = (const int*)  d_in[1];
    const int*   tgt_t  = (const int*)  d_in[2];
    const int*   src_a  = (const int*)  d_in[3];
    const int*   tgt_a  = (const int*)  d_in[4];
    const float* emb    = (const float*)d_in[5];
    const float* wihf   = (const float*)d_in[6];
    const float* whhf   = (const float*)d_in[7];
    const float* bihf   = (const float*)d_in[8];
    const float* bhhf   = (const float*)d_in[9];
    const float* wihb   = (const float*)d_in[10];
    const float* whhb   = (const float*)d_in[11];
    const float* bihb   = (const float*)d_in[12];
    const float* bhhb   = (const float*)d_in[13];
    const float* w2     = (const float*)d_in[14];
    const float* rank_w = (const float*)d_in[15];
    const float* rank_b = (const float*)d_in[16];
    float* out = (float*)d_out;

    const int scanSmem = (24*260 + 32*260) * sizeof(float);  // 58240
    cudaFuncSetAttribute(k_scan, cudaFuncAttributeMaxDynamicSharedMemorySize, scanSmem);

    k_init<<<96, 256>>>();
    k_gi<<<dim3(128, 12, 6), 256>>>(cm_tok, src_t, tgt_t, emb, wihf, bihf, wihb, bihb);
    k_scan<<<192, 256, scanSmem>>>(whhf, whhb, bhhf, bhhb, w2);  // all 6 instances
    k_sim<<<dim3(8, 32, 2), 256>>>(src_a, tgt_a, w2);
    k_reduce<<<dim3(32, 2), 256>>>();
    k_final<<<1, 256>>>(rank_w, rank_b, out);
}